// round 1
// baseline (speedup 1.0000x reference)
#include <cuda_runtime.h>
#include <cstdint>

#define NN 100000
#define NE 1600000
#define DH 64          // D_IN == HID == 64
#define F1 256

typedef unsigned long long ull;

__device__ __forceinline__ ull pack2(float x) {
    ull r; asm("mov.b64 %0,{%1,%1};" : "=l"(r) : "f"(x)); return r;
}
__device__ __forceinline__ void ffma2(ull& d, ull a, ull b) {
    asm("fma.rn.f32x2 %0,%1,%2,%0;" : "+l"(d) : "l"(a), "l"(b));
}
__device__ __forceinline__ float2 unpack2(ull v) {
    float2 r; asm("mov.b64 {%0,%1},%2;" : "=f"(r.x), "=f"(r.y) : "l"(v)); return r;
}

// ---------------- scratch (static device globals; no allocation) ----------------
__device__ int   g_deg[NN];
__device__ int   g_scan[NN];
__device__ int   g_bsum[128];
__device__ int   g_rowptr[NN + 1];
__device__ int   g_cursor[NN];
__device__ int   g_srcidx[NE];
__device__ float g_dinv[NN];
__device__ float g_h[NN * DH];      // GEMM output (pre-scaled by dinv)
__device__ float g_hagg[NN * DH];   // aggregation output
__device__ float g_ssq;

// ---------------- setup kernels ----------------
__global__ void k_init() {
    int i = blockIdx.x * blockDim.x + threadIdx.x;
    if (i < NN) { g_deg[i] = 0; g_cursor[i] = 0; }
    if (i == 0) g_ssq = 0.f;
}

__global__ void k_hist(const int* __restrict__ ei) {
    int e = blockIdx.x * blockDim.x + threadIdx.x;
    if (e < NE) atomicAdd(&g_deg[ei[NE + e]], 1);   // col = target
}

__global__ void k_scan1() {
    __shared__ int s[1024];
    int i = blockIdx.x * 1024 + threadIdx.x;
    int v = (i < NN) ? g_deg[i] : 0;
    s[threadIdx.x] = v;
    __syncthreads();
    #pragma unroll
    for (int off = 1; off < 1024; off <<= 1) {
        int t = (threadIdx.x >= off) ? s[threadIdx.x - off] : 0;
        __syncthreads();
        s[threadIdx.x] += t;
        __syncthreads();
    }
    if (i < NN) g_scan[i] = s[threadIdx.x];
    if (threadIdx.x == 1023) g_bsum[blockIdx.x] = s[1023];
}

__global__ void k_scan2(int nb) {
    if (threadIdx.x == 0 && blockIdx.x == 0) {
        int acc = 0;
        for (int b = 0; b < nb; b++) { int t = g_bsum[b]; g_bsum[b] = acc; acc += t; }
    }
}

__global__ void k_scan3() {
    int i = blockIdx.x * 1024 + threadIdx.x;
    if (i < NN) {
        int d = g_deg[i];
        int excl = g_scan[i] - d + g_bsum[blockIdx.x];
        g_rowptr[i] = excl;
        if (i == NN - 1) g_rowptr[NN] = excl + d;
        g_dinv[i] = rsqrtf((float)(d + 1));  // +1 self-loop
    }
}

__global__ void k_csr(const int* __restrict__ ei) {
    int e = blockIdx.x * blockDim.x + threadIdx.x;
    if (e < NE) {
        int r = ei[e];          // source
        int c = ei[NE + e];     // target
        int p = g_rowptr[c] + atomicAdd(&g_cursor[c], 1);
        g_srcidx[p] = r;
    }
}

// ---------------- GEMM: out[n][f] = dinv[n] * sum_k X[n][k]*W[k][f] ----------------
// Block: 256 threads, 64-node tile, full 64-feature width. 4x4 register tile, f32x2 FMA.
__global__ void __launch_bounds__(256) k_gemm64(const float* __restrict__ X,
                                                const float* __restrict__ W,
                                                float* __restrict__ out) {
    __shared__ float ws[64 * 64];     // ws[k][f]
    __shared__ float xs[64 * 68];     // xs[n][k], stride 68 (pad)
    int tid = threadIdx.x;
    int nb = blockIdx.x * 64;

    // load W (4096 floats) via float4
    const float4* W4 = (const float4*)W;
    float4* ws4 = (float4*)ws;
    #pragma unroll
    for (int j = 0; j < 4; j++) ws4[tid + j * 256] = W4[tid + j * 256];

    // load X tile (64 x 64)
    #pragma unroll
    for (int j = 0; j < 4; j++) {
        int lin = tid + j * 256;          // float4 index (1024 total)
        int n = lin >> 4, k4 = (lin & 15) * 4;
        float4 v = make_float4(0.f, 0.f, 0.f, 0.f);
        if (nb + n < NN) v = *(const float4*)&X[(size_t)(nb + n) * DH + k4];
        xs[n * 68 + k4 + 0] = v.x; xs[n * 68 + k4 + 1] = v.y;
        xs[n * 68 + k4 + 2] = v.z; xs[n * 68 + k4 + 3] = v.w;
    }
    __syncthreads();

    int ty = tid >> 4, tx = tid & 15;
    int n0 = ty * 4, f0 = tx * 4;
    ull acc[4][2] = {};
    #pragma unroll 16
    for (int k = 0; k < 64; k++) {
        ull wp0 = *(const ull*)&ws[k * 64 + f0];
        ull wp1 = *(const ull*)&ws[k * 64 + f0 + 2];
        #pragma unroll
        for (int i = 0; i < 4; i++) {
            ull xp = pack2(xs[(n0 + i) * 68 + k]);
            ffma2(acc[i][0], xp, wp0);
            ffma2(acc[i][1], xp, wp1);
        }
    }
    #pragma unroll
    for (int i = 0; i < 4; i++) {
        int n = nb + n0 + i;
        if (n < NN) {
            float s = g_dinv[n];
            float2 p0 = unpack2(acc[i][0]), p1 = unpack2(acc[i][1]);
            float4 o = make_float4(p0.x * s, p0.y * s, p1.x * s, p1.y * s);
            *(float4*)&out[(size_t)n * DH + f0] = o;
        }
    }
}

// ---------------- Aggregation: out[n] = relu(dinv[n]*(hs[n] + sum_src hs[src]) + b) ----------------
// Warp per node; lane owns 2 features. Source indices broadcast via shuffle.
__global__ void __launch_bounds__(256) k_agg(const float* __restrict__ hs,
                                             const float* __restrict__ bias,
                                             float* __restrict__ out) {
    int warp = (blockIdx.x * blockDim.x + threadIdx.x) >> 5;
    int lane = threadIdx.x & 31;
    if (warp >= NN) return;
    int n = warp;
    int f0 = lane * 2;

    float2 acc = *(const float2*)&hs[(size_t)n * DH + f0];   // self-loop term
    int beg = g_rowptr[n], end = g_rowptr[n + 1];
    for (int j = beg; j < end; j += 32) {
        int cnt = min(32, end - j);
        int s = (j + lane < end) ? g_srcidx[j + lane] : 0;
        for (int t = 0; t < cnt; t++) {
            int ss = __shfl_sync(0xffffffffu, s, t);
            float2 v = *(const float2*)&hs[(size_t)ss * DH + f0];
            acc.x += v.x; acc.y += v.y;
        }
    }
    float d = g_dinv[n];
    float ox = fmaxf(fmaf(acc.x, d, bias[f0]), 0.f);
    float oy = fmaxf(fmaf(acc.y, d, bias[f0 + 1]), 0.f);
    *(float2*)&out[(size_t)n * DH + f0] = make_float2(ox, oy);
}

// ---------------- Fused MLP head: o[n] = relu(h[n] @ fc1_w + fc1_b) . fc2_w + fc2_b ----------------
// 256 threads = 256 fc1 output features. W1 column in registers. 8 nodes per group.
__global__ void __launch_bounds__(256) k_fc(const float* __restrict__ H,
                                            const float* __restrict__ W1f,
                                            const float* __restrict__ b1f,
                                            const float* __restrict__ w2,
                                            const float* __restrict__ b2,
                                            float* __restrict__ out) {
    __shared__ float xs[64 * 10];    // (k, n) at xs[k*10 + n], n=0..7 (pad to 10)
    __shared__ float red[8][8];
    int tid = threadIdx.x, lane = tid & 31, wid = tid >> 5;
    int f = tid;

    float w[64];
    #pragma unroll
    for (int k = 0; k < 64; k++) w[k] = W1f[k * F1 + f];
    float bf = b1f[f], w2f = w2[f], b2v = b2[0];
    float lssq = 0.f;

    for (int g = blockIdx.x; g < NN / 8; g += gridDim.x) {
        int nbase = g * 8;
        // warp wid loads node nbase+wid (64 floats as float2 per lane)
        {
            float2 v = *(const float2*)&H[(size_t)(nbase + wid) * DH + lane * 2];
            xs[(2 * lane) * 10 + wid] = v.x;
            xs[(2 * lane + 1) * 10 + wid] = v.y;
        }
        __syncthreads();

        ull a0 = 0, a1 = 0, a2 = 0, a3 = 0;
        #pragma unroll
        for (int k = 0; k < 64; k++) {
            const ull* xp = (const ull*)&xs[k * 10];   // k*10 even -> 8B aligned
            ull wp = pack2(w[k]);
            ffma2(a0, wp, xp[0]);
            ffma2(a1, wp, xp[1]);
            ffma2(a2, wp, xp[2]);
            ffma2(a3, wp, xp[3]);
        }
        float2 t0 = unpack2(a0), t1 = unpack2(a1), t2 = unpack2(a2), t3 = unpack2(a3);
        float c[8];
        c[0] = fmaxf(t0.x + bf, 0.f) * w2f;  c[1] = fmaxf(t0.y + bf, 0.f) * w2f;
        c[2] = fmaxf(t1.x + bf, 0.f) * w2f;  c[3] = fmaxf(t1.y + bf, 0.f) * w2f;
        c[4] = fmaxf(t2.x + bf, 0.f) * w2f;  c[5] = fmaxf(t2.y + bf, 0.f) * w2f;
        c[6] = fmaxf(t3.x + bf, 0.f) * w2f;  c[7] = fmaxf(t3.y + bf, 0.f) * w2f;
        #pragma unroll
        for (int i = 0; i < 8; i++) {
            #pragma unroll
            for (int o = 16; o > 0; o >>= 1) c[i] += __shfl_down_sync(0xffffffffu, c[i], o);
        }
        if (lane == 0) {
            #pragma unroll
            for (int i = 0; i < 8; i++) red[wid][i] = c[i];
        }
        __syncthreads();
        if (tid < 8) {
            float o = b2v;
            #pragma unroll
            for (int wq = 0; wq < 8; wq++) o += red[wq][tid];
            out[nbase + tid] = o;
            lssq += o * o;
        }
        __syncthreads();
    }
    // block-level ssq reduce (only warp 0 lanes 0..7 have nonzero; others are 0)
    #pragma unroll
    for (int o = 16; o > 0; o >>= 1) lssq += __shfl_down_sync(0xffffffffu, lssq, o);
    if (lane == 0 && lssq != 0.f) atomicAdd(&g_ssq, lssq);
}

__global__ void k_norm(float* __restrict__ out) {
    float s = 1.f / fmaxf(sqrtf(g_ssq), 1e-12f);
    int i = blockIdx.x * blockDim.x + threadIdx.x;
    if (i < NN) out[i] *= s;
}

// ---------------- launcher ----------------
extern "C" void kernel_launch(void* const* d_in, const int* in_sizes, int n_in,
                              void* d_out, int out_size) {
    const float* x    = (const float*)d_in[0];
    const int*   ei   = (const int*)d_in[1];
    const float* W1   = (const float*)d_in[2];
    const float* b1   = (const float*)d_in[3];
    const float* W2   = (const float*)d_in[4];
    const float* b2   = (const float*)d_in[5];
    const float* fc1w = (const float*)d_in[6];
    const float* fc1b = (const float*)d_in[7];
    const float* fc2w = (const float*)d_in[8];
    const float* fc2b = (const float*)d_in[9];
    float* out = (float*)d_out;

    void *p_h = nullptr, *p_hagg = nullptr;
    cudaGetSymbolAddress(&p_h, g_h);
    cudaGetSymbolAddress(&p_hagg, g_hagg);
    float* h    = (float*)p_h;
    float* hagg = (float*)p_hagg;

    const int nb_scan = (NN + 1023) / 1024;   // 98

    k_init<<<(NN + 255) / 256, 256>>>();
    k_hist<<<(NE + 255) / 256, 256>>>(ei);
    k_scan1<<<nb_scan, 1024>>>();
    k_scan2<<<1, 32>>>(nb_scan);
    k_scan3<<<nb_scan, 1024>>>();
    k_csr<<<(NE + 255) / 256, 256>>>(ei);

    const int gemm_blocks = (NN + 63) / 64;   // 1563
    const int agg_blocks  = (NN + 7) / 8;     // 12500 (8 warps/block)

    // layer 1
    k_gemm64<<<gemm_blocks, 256>>>(x, W1, h);
    k_agg<<<agg_blocks, 256>>>(h, b1, hagg);
    // layer 2
    k_gemm64<<<gemm_blocks, 256>>>(hagg, W2, h);
    k_agg<<<agg_blocks, 256>>>(h, b2, hagg);
    // fused MLP head + ssq
    k_fc<<<592, 256>>>(hagg, fc1w, fc1b, fc2w, fc2b, out);
    // global L2 normalize
    k_norm<<<(NN + 255) / 256, 256>>>(out);
}